// round 4
// baseline (speedup 1.0000x reference)
#include <cuda_runtime.h>
#include <math.h>

#define NN 100000
#define EE 1600000

// ---------------- static device scratch (no allocation allowed) ----------------
__device__ float4 g_h4[NN * 16];      // per-layer transformed features (row stride C floats)
__device__ float4 g_a4[NN * 16];      // aggregation output (next layer input, pre-bias)
__device__ float4 g_als4[NN];         // attention logits (src side), one float4 = 4 heads
__device__ float4 g_ald4[NN];         // attention logits (dst side)
__device__ int    g_rowptr[NN + 1];
__device__ int    g_cursor[NN];
__device__ int    g_col[EE];
__device__ int    g_bsum[512];
__device__ float  g_pool[64 * 8];
__device__ float  g_cnt[64];

// ---------------- CSR build ----------------
__global__ void k_zero_cursor() {
    int i = blockIdx.x * 256 + threadIdx.x;
    if (i < NN) g_cursor[i] = 0;
}

// edge_index is int32 (JAX x64-disabled downgrades the requested int64)
__global__ void k_count(const int* __restrict__ ei) {
    int e = blockIdx.x * 256 + threadIdx.x;
    if (e < EE) atomicAdd(&g_cursor[ei[EE + e]], 1);
}

__global__ void k_scan1() {
    __shared__ int sm[256];
    int t = threadIdx.x;
    int i = blockIdx.x * 256 + t;
    int v = (i < NN) ? g_cursor[i] : 0;
    sm[t] = v;
    __syncthreads();
    for (int d = 1; d < 256; d <<= 1) {
        int x = (t >= d) ? sm[t - d] : 0;
        __syncthreads();
        sm[t] += x;
        __syncthreads();
    }
    if (i < NN) g_rowptr[i] = sm[t] - v;   // block-local exclusive
    if (t == 255) g_bsum[blockIdx.x] = sm[255];
}

__global__ void k_scan2() {
    __shared__ int sm[512];
    int t = threadIdx.x;
    int v = (t < 391) ? g_bsum[t] : 0;
    sm[t] = v;
    __syncthreads();
    for (int d = 1; d < 512; d <<= 1) {
        int x = (t >= d) ? sm[t - d] : 0;
        __syncthreads();
        sm[t] += x;
        __syncthreads();
    }
    if (t < 391) g_bsum[t] = sm[t] - v;    // exclusive block offsets
    if (t == 511) g_rowptr[NN] = sm[511];  // total == EE
}

__global__ void k_scan3() {
    int i = blockIdx.x * 256 + threadIdx.x;
    if (i < NN) {
        g_rowptr[i] += g_bsum[blockIdx.x];
        g_cursor[i] = 0;
    }
}

__global__ void k_scatter(const int* __restrict__ ei) {
    int e = blockIdx.x * 256 + threadIdx.x;
    if (e < EE) {
        int d = ei[EE + e];
        int p = g_rowptr[d] + atomicAdd(&g_cursor[d], 1);
        g_col[p] = ei[e];
    }
}

// ---------------- fused GEMM (h = relu(in+b_prev) @ W) + attention-logit epilogue ----------------
template <int K, int C, bool RELU_IN>
__global__ __launch_bounds__(128) void k_gemm(const float* __restrict__ in_ext,
                                              const float* __restrict__ W,
                                              const float* __restrict__ asrc,
                                              const float* __restrict__ adst,
                                              const float* __restrict__ bin) {
    constexpr int OC = C / 4;  // channels per head
    __shared__ float4 sW4[K * C / 4];
    __shared__ float sIn[8][132];
    __shared__ float sB[K > 0 ? K : 1];
    __shared__ float sA[C];
    __shared__ float sD[C];
    float* sW = (float*)sW4;

    const float* in = RELU_IN ? (const float*)g_a4 : in_ext;
    int t = threadIdx.x;
    for (int i = t; i < K * C; i += 128) sW[i] = W[i];
    for (int i = t; i < C; i += 128) { sA[i] = asrc[i]; sD[i] = adst[i]; }
    if (RELU_IN) {
        for (int i = t; i < K; i += 128) sB[i] = bin[i];
    }
    __syncthreads();

    int row = blockIdx.x * 128 + t;
    float acc[C];
#pragma unroll
    for (int c = 0; c < C; c++) acc[c] = 0.f;

    for (int k0 = 0; k0 < K; k0 += 8) {
#pragma unroll
        for (int i = 0; i < 8; i++) {
            int idx = i * 128 + t;
            int r = idx >> 3;
            int kk = idx & 7;
            int gr = blockIdx.x * 128 + r;
            float v = 0.f;
            if (gr < NN) {
                v = in[gr * K + k0 + kk];
                if (RELU_IN) v = fmaxf(v + sB[k0 + kk], 0.f);
            }
            sIn[kk][r] = v;
        }
        __syncthreads();
#pragma unroll
        for (int kk = 0; kk < 8; kk++) {
            float a = sIn[kk][t];
            const float4* wr = &sW4[(k0 + kk) * (C / 4)];
#pragma unroll
            for (int c4 = 0; c4 < C / 4; c4++) {
                float4 w = wr[c4];
                acc[c4 * 4 + 0] += a * w.x;
                acc[c4 * 4 + 1] += a * w.y;
                acc[c4 * 4 + 2] += a * w.z;
                acc[c4 * 4 + 3] += a * w.w;
            }
        }
        __syncthreads();
    }

    if (row < NN) {
#pragma unroll
        for (int c4 = 0; c4 < C / 4; c4++) {
            float4 o;
            o.x = acc[c4 * 4 + 0];
            o.y = acc[c4 * 4 + 1];
            o.z = acc[c4 * 4 + 2];
            o.w = acc[c4 * 4 + 3];
            g_h4[row * (C / 4) + c4] = o;
        }
        float4 so, dto;
#pragma unroll
        for (int hh = 0; hh < 4; hh++) {
            float s = 0.f, d = 0.f;
#pragma unroll
            for (int j = 0; j < OC; j++) {
                s += acc[hh * OC + j] * sA[hh * OC + j];
                d += acc[hh * OC + j] * sD[hh * OC + j];
            }
            ((float*)&so)[hh] = s;
            ((float*)&dto)[hh] = d;
        }
        g_als4[row] = so;
        g_ald4[row] = dto;
    }
}

// ---------------- attention aggregation: warp per dst node, 3-phase softmax ----------------
__device__ __forceinline__ float4 lrelu4(float4 v) {
    v.x = fmaxf(v.x, 0.2f * v.x);
    v.y = fmaxf(v.y, 0.2f * v.y);
    v.z = fmaxf(v.z, 0.2f * v.z);
    v.w = fmaxf(v.w, 0.2f * v.w);
    return v;
}
__device__ __forceinline__ float hsel(float4 v, int h) {
    return (h == 0) ? v.x : (h == 1) ? v.y : (h == 2) ? v.z : v.w;
}

template <int C, int OC>
__global__ __launch_bounds__(256) void k_agg() {
    __shared__ float4 sp[8][32];  // per-warp per-edge exp(e - m) for 4 heads
    int warp = threadIdx.x >> 5;
    int lane = threadIdx.x & 31;
    int n = blockIdx.x * 8 + warp;
    if (n >= NN) return;

    const float*  gh  = (const float*)g_h4;
    const float2* gh2 = (const float2*)g_h4;

    int c0, head;
    if (C == 64) { c0 = lane * 2; head = lane >> 3; }
    else { c0 = (lane < C) ? lane : 0; head = c0 / OC; }

    float4 ald4 = g_ald4[n];
    float4 asn  = g_als4[n];
    float4 es4;
    es4.x = asn.x + ald4.x; es4.y = asn.y + ald4.y;
    es4.z = asn.z + ald4.z; es4.w = asn.w + ald4.w;
    es4 = lrelu4(es4);
    float4 m4 = es4;

    int start = g_rowptr[n];
    int end = g_rowptr[n + 1];

    // Phase A: per-head max over incoming edges (edge-parallel across lanes)
    for (int j0 = start; j0 < end; j0 += 32) {
        int lj = j0 + lane;
        int src = (lj < end) ? g_col[lj] : 0;
        float4 a4 = g_als4[src];
        float4 e4;
        e4.x = a4.x + ald4.x; e4.y = a4.y + ald4.y;
        e4.z = a4.z + ald4.z; e4.w = a4.w + ald4.w;
        e4 = lrelu4(e4);
        if (lj >= end) { e4.x = -1e30f; e4.y = -1e30f; e4.z = -1e30f; e4.w = -1e30f; }
        m4.x = fmaxf(m4.x, e4.x); m4.y = fmaxf(m4.y, e4.y);
        m4.z = fmaxf(m4.z, e4.z); m4.w = fmaxf(m4.w, e4.w);
    }
#pragma unroll
    for (int d = 16; d; d >>= 1) {
        m4.x = fmaxf(m4.x, __shfl_xor_sync(0xffffffffu, m4.x, d));
        m4.y = fmaxf(m4.y, __shfl_xor_sync(0xffffffffu, m4.y, d));
        m4.z = fmaxf(m4.z, __shfl_xor_sync(0xffffffffu, m4.z, d));
        m4.w = fmaxf(m4.w, __shfl_xor_sync(0xffffffffu, m4.w, d));
    }

    // self-loop contribution
    float4 ps4;
    ps4.x = __expf(es4.x - m4.x);
    ps4.y = __expf(es4.y - m4.y);
    ps4.z = __expf(es4.z - m4.z);
    ps4.w = __expf(es4.w - m4.w);
    float ps = hsel(ps4, head);
    float4 s4;
    if (lane == 0) s4 = ps4;
    else { s4.x = 0.f; s4.y = 0.f; s4.z = 0.f; s4.w = 0.f; }

    float accx, accy = 0.f;
    if (C == 64) {
        float2 hv = gh2[n * 32 + lane];
        accx = ps * hv.x;
        accy = ps * hv.y;
    } else {
        accx = ps * gh[n * C + c0];
    }

    // Phase B (exp + sum, edge-parallel) fused with Phase C (channel-parallel gather)
    for (int j0 = start; j0 < end; j0 += 32) {
        int lj = j0 + lane;
        bool vld = lj < end;
        int src = vld ? g_col[lj] : 0;
        float4 a4 = g_als4[src];
        float4 e4;
        e4.x = a4.x + ald4.x; e4.y = a4.y + ald4.y;
        e4.z = a4.z + ald4.z; e4.w = a4.w + ald4.w;
        e4 = lrelu4(e4);
        float4 p4;
        p4.x = vld ? __expf(e4.x - m4.x) : 0.f;
        p4.y = vld ? __expf(e4.y - m4.y) : 0.f;
        p4.z = vld ? __expf(e4.z - m4.z) : 0.f;
        p4.w = vld ? __expf(e4.w - m4.w) : 0.f;
        s4.x += p4.x; s4.y += p4.y; s4.z += p4.z; s4.w += p4.w;
        sp[warp][lane] = p4;
        __syncwarp();

        int cnt = min(32, end - j0);
        const float* pw = (const float*)&sp[warp][0];
        int jj = 0;
        for (; jj + 4 <= cnt; jj += 4) {
            int s0 = __shfl_sync(0xffffffffu, src, jj + 0);
            int s1 = __shfl_sync(0xffffffffu, src, jj + 1);
            int s2 = __shfl_sync(0xffffffffu, src, jj + 2);
            int s3 = __shfl_sync(0xffffffffu, src, jj + 3);
            float p0 = pw[(jj + 0) * 4 + head];
            float p1 = pw[(jj + 1) * 4 + head];
            float p2 = pw[(jj + 2) * 4 + head];
            float p3 = pw[(jj + 3) * 4 + head];
            if (C == 64) {
                float2 h0 = gh2[s0 * 32 + lane];
                float2 h1 = gh2[s1 * 32 + lane];
                float2 h2 = gh2[s2 * 32 + lane];
                float2 h3 = gh2[s3 * 32 + lane];
                accx += p0 * h0.x; accy += p0 * h0.y;
                accx += p1 * h1.x; accy += p1 * h1.y;
                accx += p2 * h2.x; accy += p2 * h2.y;
                accx += p3 * h3.x; accy += p3 * h3.y;
            } else {
                float h0 = gh[s0 * C + c0];
                float h1 = gh[s1 * C + c0];
                float h2 = gh[s2 * C + c0];
                float h3 = gh[s3 * C + c0];
                accx += p0 * h0;
                accx += p1 * h1;
                accx += p2 * h2;
                accx += p3 * h3;
            }
        }
        for (; jj < cnt; jj++) {
            int s0 = __shfl_sync(0xffffffffu, src, jj);
            float p0 = pw[jj * 4 + head];
            if (C == 64) {
                float2 h0 = gh2[s0 * 32 + lane];
                accx += p0 * h0.x;
                accy += p0 * h0.y;
            } else {
                accx += p0 * gh[s0 * C + c0];
            }
        }
        __syncwarp();
    }

#pragma unroll
    for (int d = 16; d; d >>= 1) {
        s4.x += __shfl_xor_sync(0xffffffffu, s4.x, d);
        s4.y += __shfl_xor_sync(0xffffffffu, s4.y, d);
        s4.z += __shfl_xor_sync(0xffffffffu, s4.z, d);
        s4.w += __shfl_xor_sync(0xffffffffu, s4.w, d);
    }
    float inv = 1.0f / hsel(s4, head);

    if (C == 64) {
        float2 o;
        o.x = accx * inv;
        o.y = accy * inv;
        ((float2*)g_a4)[n * 32 + lane] = o;
    } else if (lane < C) {
        ((float*)g_a4)[n * C + c0] = accx * inv;
    }
}

// ---------------- pooling + FC ----------------
__global__ void k_zero_pool() {
    int t = threadIdx.x;
    if (t < 512) g_pool[t] = 0.f;
    if (t < 64) g_cnt[t] = 0.f;
}

// batch is int32 (JAX x64-disabled downgrade, same as edge_index)
__global__ void k_pool(const int* __restrict__ batch, const float* __restrict__ b4) {
    int nn = blockIdx.x * 256 + threadIdx.x;
    if (nn >= NN) return;
    const float* ga = (const float*)g_a4;
    int b = batch[nn];
    atomicAdd(&g_cnt[b], 1.0f);
#pragma unroll
    for (int c = 0; c < 8; c++) {
        float v = fmaxf(ga[nn * 8 + c] + b4[c], 0.f);
        atomicAdd(&g_pool[b * 8 + c], v);
    }
}

__global__ void k_fc(const float* __restrict__ Wfc, const float* __restrict__ bfc,
                     float* __restrict__ out) {
    int id = blockIdx.x * 256 + threadIdx.x;
    if (id >= 64 * 32) return;
    int b = id >> 5;
    int o = id & 31;
    float invc = 1.0f / fmaxf(g_cnt[b], 1.0f);
    float acc = bfc[o];
#pragma unroll
    for (int c = 0; c < 8; c++) acc += (g_pool[b * 8 + c] * invc) * Wfc[c * 32 + o];
    out[id] = acc;
}

// ---------------- launch ----------------
extern "C" void kernel_launch(void* const* d_in, const int* in_sizes, int n_in,
                              void* d_out, int out_size) {
    const float* x     = (const float*)d_in[0];
    const int*   ei    = (const int*)d_in[1];     // int32 edge_index [2, E]
    const int*   batch = (const int*)d_in[2];     // int32 batch [N]
    const float* W1  = (const float*)d_in[3];
    const float* as1 = (const float*)d_in[4];
    const float* ad1 = (const float*)d_in[5];
    const float* b1  = (const float*)d_in[6];
    const float* W2  = (const float*)d_in[7];
    const float* as2 = (const float*)d_in[8];
    const float* ad2 = (const float*)d_in[9];
    const float* b2  = (const float*)d_in[10];
    const float* W3  = (const float*)d_in[11];
    const float* as3 = (const float*)d_in[12];
    const float* ad3 = (const float*)d_in[13];
    const float* b3  = (const float*)d_in[14];
    const float* W4  = (const float*)d_in[15];
    const float* as4 = (const float*)d_in[16];
    const float* ad4 = (const float*)d_in[17];
    const float* b4  = (const float*)d_in[18];
    const float* Wfc = (const float*)d_in[19];
    const float* bfc = (const float*)d_in[20];

    const int NBLK = (NN + 255) / 256;   // 391
    const int EBLK = (EE + 255) / 256;   // 6250

    // CSR by destination (shared by all 4 layers)
    k_zero_cursor<<<NBLK, 256>>>();
    k_count<<<EBLK, 256>>>(ei);
    k_scan1<<<NBLK, 256>>>();
    k_scan2<<<1, 512>>>();
    k_scan3<<<NBLK, 256>>>();
    k_scatter<<<EBLK, 256>>>(ei);

    const int GBLK = (NN + 127) / 128;   // 782
    const int ABLK = (NN + 7) / 8;       // 12500

    // layer 1: 128 -> 4x16
    k_gemm<128, 64, false><<<GBLK, 128>>>(x, W1, as1, ad1, nullptr);
    k_agg<64, 16><<<ABLK, 256>>>();
    // layer 2: 64 -> 4x8  (relu(prev + b1) fused into GEMM load)
    k_gemm<64, 32, true><<<GBLK, 128>>>(nullptr, W2, as2, ad2, b1);
    k_agg<32, 8><<<ABLK, 256>>>();
    // layer 3: 32 -> 4x4
    k_gemm<32, 16, true><<<GBLK, 128>>>(nullptr, W3, as3, ad3, b2);
    k_agg<16, 4><<<ABLK, 256>>>();
    // layer 4: 16 -> 4x2
    k_gemm<16, 8, true><<<GBLK, 128>>>(nullptr, W4, as4, ad4, b3);
    k_agg<8, 2><<<ABLK, 256>>>();

    // global mean pool (relu(prev + b4)) + FC
    k_zero_pool<<<1, 512>>>();
    k_pool<<<NBLK, 256>>>(batch, b4);
    k_fc<<<8, 256>>>(Wfc, bfc, (float*)d_out);
}